// round 2
// baseline (speedup 1.0000x reference)
#include <cuda_runtime.h>
#include <math.h>

// ---------------- problem constants ----------------
#define BB   64          // batch
#define NN   256         // sequence length (K in reference)
#define CC   512         // input channels
#define OO   1024        // qkv channels (2*OUT_PLANES)
#define GG   8           // groups
#define HC   32          // half group planes (q/k channels per group)
#define VC   64          // v channels per group
#define EPSV 1e-5f
#define F_QR 0.1f
#define F_KR 0.1f
#define F_SVE 0.1f
#define F_SV  1.0f

// ---------------- scratch (static device allocations) ----------------
__device__ float d_qkv[(size_t)BB * OO * NN];                 // 64 MB
__device__ float d_bnA[OO];
__device__ float d_bnC[OO];
__device__ float d_stk[(size_t)3 * BB * GG * NN * NN];        // 402 MB (qk,qr,kr raw)
__device__ float d_simstats[48];                              // 24 ch x (sum,sumsq)
__device__ float d_sv [(size_t)BB * GG * VC * NN];            // 33.5 MB
__device__ float d_sve[(size_t)BB * GG * VC * NN];            // 33.5 MB
__device__ float d_outA[OO];
__device__ float d_outC[OO];

// ---------------- K0: zero sim stats (must run every replay) ----------------
__global__ void k_zero_stats() {
    int t = threadIdx.x;
    if (t < 48) d_simstats[t] = 0.0f;
}

// ---------------- K1: qkv GEMM  qkv[b][o][n] = sum_c w[o][c]*x[b][n][c] ----------------
#define GM 64
#define GN 64
#define GK 16
__global__ void k_qkv_gemm(const float* __restrict__ x, const float* __restrict__ w) {
    __shared__ float Xs[GK][GM + 4];
    __shared__ float Ws[GK][GN + 4];
    int b  = blockIdx.z;
    int n0 = blockIdx.x * GM;
    int o0 = blockIdx.y * GN;
    int tid = threadIdx.x;
    int tx = tid & 15, ty = tid >> 4;
    float acc[4][4];
#pragma unroll
    for (int i = 0; i < 4; i++)
#pragma unroll
        for (int j = 0; j < 4; j++) acc[i][j] = 0.0f;

    const float* xb = x + ((size_t)b * NN + n0) * CC;
    int lr = tid >> 2;            // 0..63
    int lc = (tid & 3) * 4;       // 0,4,8,12

    for (int c0 = 0; c0 < CC; c0 += GK) {
        float4 v = *(const float4*)(xb + (size_t)lr * CC + c0 + lc);
        Xs[lc + 0][lr] = v.x; Xs[lc + 1][lr] = v.y; Xs[lc + 2][lr] = v.z; Xs[lc + 3][lr] = v.w;
        float4 u = *(const float4*)(w + (size_t)(o0 + lr) * CC + c0 + lc);
        Ws[lc + 0][lr] = u.x; Ws[lc + 1][lr] = u.y; Ws[lc + 2][lr] = u.z; Ws[lc + 3][lr] = u.w;
        __syncthreads();
#pragma unroll
        for (int kk = 0; kk < GK; kk++) {
            float4 a4 = *(const float4*)&Xs[kk][tx * 4];
            float4 b4 = *(const float4*)&Ws[kk][ty * 4];
            float a[4] = {a4.x, a4.y, a4.z, a4.w};
            float bbv[4] = {b4.x, b4.y, b4.z, b4.w};
#pragma unroll
            for (int j = 0; j < 4; j++)
#pragma unroll
                for (int i = 0; i < 4; i++) acc[j][i] += a[i] * bbv[j];
        }
        __syncthreads();
    }
    float* outp = d_qkv + ((size_t)b * OO + o0) * NN + n0;
#pragma unroll
    for (int j = 0; j < 4; j++) {
        float4 v = make_float4(acc[j][0], acc[j][1], acc[j][2], acc[j][3]);
        *(float4*)(outp + (size_t)(ty * 4 + j) * NN + tx * 4) = v;
    }
}

// ---------------- block reduce helper ----------------
__device__ __forceinline__ void block_reduce2(float& s, float& ss, float* sh) {
    int tid = threadIdx.x;
    float* shs = sh;         // 256
    float* shq = sh + 256;   // 256
    shs[tid] = s; shq[tid] = ss;
    __syncthreads();
    for (int step = 128; step > 0; step >>= 1) {
        if (tid < step) { shs[tid] += shs[tid + step]; shq[tid] += shq[tid + step]; }
        __syncthreads();
    }
    s = shs[0]; ss = shq[0];
}

// ---------------- K2: qkv BN -> per-channel affine ----------------
__global__ void k_qkv_stats(const float* __restrict__ gq, const float* __restrict__ bq) {
    __shared__ float sh[512];
    int o = blockIdx.x;
    int tid = threadIdx.x;     // n index
    float s = 0.f, ss = 0.f;
    const float* base = d_qkv + (size_t)o * NN + tid;
    for (int b = 0; b < BB; b++) {
        float v = base[(size_t)b * OO * NN];
        s += v; ss += v * v;
    }
    block_reduce2(s, ss, sh);
    if (tid == 0) {
        float m = s / 16384.0f;
        float var = ss / 16384.0f - m * m;
        float a = gq[o] * rsqrtf(var + EPSV);
        d_bnA[o] = a;
        d_bnC[o] = bq[o] - m * a;
    }
}

// ---------------- K3: raw qk/qr/kr + channel stats ----------------
// grid (4 itiles of 64, G, B), 256 threads (thread = j)
__global__ void k_sim_raw(const float* __restrict__ rel) {
    extern __shared__ float sm[];
    float* qs   = sm;                 // 32*64
    float* relA = qs + 32 * 64;       // 32*320
    float* relB = relA + 32 * 320;    // 32*320
    int it = blockIdx.x, g = blockIdx.y, b = blockIdx.z;
    int i0 = it * 64;
    int tid = threadIdx.x;

    for (int idx = tid; idx < 32 * 319; idx += 256) {
        int c = idx / 319, d = idx - c * 319;
        relA[c * 320 + d] = rel[(size_t)c * 511 + i0 + d];
        relB[c * 320 + d] = rel[(size_t)(32 + c) * 511 + (192 - i0) + d];
    }
    {
        int cbase = tid >> 6, il = tid & 63;
        for (int c = cbase; c < 32; c += 4) {
            int o = g * 128 + c;
            qs[c * 64 + il] = d_bnA[o] * d_qkv[((size_t)b * OO + o) * NN + i0 + il] + d_bnC[o];
        }
    }
    float kcol[32];
#pragma unroll
    for (int c = 0; c < 32; c++) {
        int o = g * 128 + HC + c;
        kcol[c] = d_bnA[o] * d_qkv[((size_t)b * OO + o) * NN + tid] + d_bnC[o];
    }
    __syncthreads();

    float s0 = 0, q0 = 0, s1 = 0, q1 = 0, s2 = 0, q2 = 0;
    const size_t F = (size_t)BB * GG * NN * NN;
    size_t base = (((size_t)b * GG + g) * NN + i0) * NN + tid;

    for (int il = 0; il < 64; il++) {
        float aqk = 0.f, aqr = 0.f, akr = 0.f;
        const float* ra = relA + (il + 255 - tid);
        const float* rb = relB + (tid - il + 63);
#pragma unroll
        for (int c = 0; c < 32; c++) {
            float qv = qs[c * 64 + il];
            aqk += qv * kcol[c];
            aqr += qv * ra[c * 320];
            akr += kcol[c] * rb[c * 320];
        }
        aqr *= F_QR; akr *= F_KR;
        size_t off = base + (size_t)il * NN;
        d_stk[off]         = aqk;
        d_stk[F + off]     = aqr;
        d_stk[2 * F + off] = akr;
        s0 += aqk; q0 += aqk * aqk;
        s1 += aqr; q1 += aqr * aqr;
        s2 += akr; q2 += akr * akr;
    }
#pragma unroll
    for (int off = 16; off; off >>= 1) {
        s0 += __shfl_xor_sync(0xffffffffu, s0, off);
        q0 += __shfl_xor_sync(0xffffffffu, q0, off);
        s1 += __shfl_xor_sync(0xffffffffu, s1, off);
        q1 += __shfl_xor_sync(0xffffffffu, q1, off);
        s2 += __shfl_xor_sync(0xffffffffu, s2, off);
        q2 += __shfl_xor_sync(0xffffffffu, q2, off);
    }
    if ((tid & 31) == 0) {
        atomicAdd(&d_simstats[(0 * 8 + g) * 2],     s0);
        atomicAdd(&d_simstats[(0 * 8 + g) * 2 + 1], q0);
        atomicAdd(&d_simstats[(1 * 8 + g) * 2],     s1);
        atomicAdd(&d_simstats[(1 * 8 + g) * 2 + 1], q1);
        atomicAdd(&d_simstats[(2 * 8 + g) * 2],     s2);
        atomicAdd(&d_simstats[(2 * 8 + g) * 2 + 1], q2);
    }
}

// ---------------- K5: sim BN + softmax + sv + sve ----------------
// grid (8 itiles of 32, G, B), 256 threads
__global__ void k_attn(const float* __restrict__ rel,
                       const float* __restrict__ gsim, const float* __restrict__ bsim) {
    extern __shared__ float sm[];
    float* p    = sm;                   // 32*257
    float* vbs  = p + 32 * 257;         // 64*257
    float* relV = vbs + 64 * 257;       // 64*287
    float* stage = relV + 64 * 287;     // 64*33
    int it = blockIdx.x, g = blockIdx.y, b = blockIdx.z;
    int i0 = it * 32;
    int tid = threadIdx.x;

    const float NELI = 1.0f / (64.0f * 256.0f * 256.0f);
    float aS[3], cS[3];
#pragma unroll
    for (int s = 0; s < 3; s++) {
        int ch = s * 8 + g;
        float m = d_simstats[ch * 2] * NELI;
        float var = d_simstats[ch * 2 + 1] * NELI - m * m;
        float a = gsim[ch] * rsqrtf(var + EPSV);
        aS[s] = a; cS[s] = bsim[ch] - m * a;
    }

    const size_t F = (size_t)BB * GG * NN * NN;
    size_t baseL = (((size_t)b * GG + g) * NN + i0) * NN + tid;
    for (int il = 0; il < 32; il++) {
        size_t off = baseL + (size_t)il * NN;
        float L = aS[0] * d_stk[off] + cS[0]
                + aS[1] * d_stk[F + off] + cS[1]
                + aS[2] * d_stk[2 * F + off] + cS[2];
        p[il * 257 + tid] = L;
    }
    for (int c = 0; c < VC; c++) {
        int o = g * 128 + 2 * HC + c;
        vbs[c * 257 + tid] = d_bnA[o] * d_qkv[((size_t)b * OO + o) * NN + tid] + d_bnC[o];
    }
    for (int idx = tid; idx < 64 * 287; idx += 256) {
        int c = idx / 287, d = idx - c * 287;
        relV[idx] = rel[(size_t)(64 + c) * 511 + i0 + d];
    }
    __syncthreads();

    // softmax over j, one warp handles 4 rows
    int warp = tid >> 5, lane = tid & 31;
    for (int r = warp; r < 32; r += 8) {
        float* row = p + r * 257;
        float v[8];
        float mx = -1e30f;
#pragma unroll
        for (int k = 0; k < 8; k++) { v[k] = row[lane + 32 * k]; mx = fmaxf(mx, v[k]); }
#pragma unroll
        for (int off = 16; off; off >>= 1) mx = fmaxf(mx, __shfl_xor_sync(0xffffffffu, mx, off));
        float sum = 0.f;
#pragma unroll
        for (int k = 0; k < 8; k++) { v[k] = expf(v[k] - mx); sum += v[k]; }
#pragma unroll
        for (int off = 16; off; off >>= 1) sum += __shfl_xor_sync(0xffffffffu, sum, off);
        float inv = 1.0f / sum;
#pragma unroll
        for (int k = 0; k < 8; k++) row[lane + 32 * k] = v[k] * inv;
    }
    __syncthreads();

    // sv / sve : thread -> (c = tid%64, il = tid/64 + 4k)
    int c = tid & 63;
    int il0 = tid >> 6;
    float asv[8], asve[8];
#pragma unroll
    for (int k = 0; k < 8; k++) { asv[k] = 0.f; asve[k] = 0.f; }
    for (int j = 0; j < 256; j++) {
        float vb = vbs[c * 257 + j];
#pragma unroll
        for (int k = 0; k < 8; k++) {
            int il = il0 + 4 * k;
            float pv = p[il * 257 + j];
            asv[k]  += pv * vb;
            asve[k] += pv * relV[c * 287 + il + 255 - j];
        }
    }
    size_t baseO = (((size_t)b * GG + g) * VC) * NN + i0;

#pragma unroll
    for (int k = 0; k < 8; k++) stage[c * 33 + il0 + 4 * k] = asv[k] * F_SV;
    __syncthreads();
    for (int idx = tid; idx < 2048; idx += 256) {
        int cc = idx >> 5, ii = idx & 31;
        d_sv[baseO + (size_t)cc * NN + ii] = stage[cc * 33 + ii];
    }
    __syncthreads();
#pragma unroll
    for (int k = 0; k < 8; k++) stage[c * 33 + il0 + 4 * k] = asve[k] * F_SVE;
    __syncthreads();
    for (int idx = tid; idx < 2048; idx += 256) {
        int cc = idx >> 5, ii = idx & 31;
        d_sve[baseO + (size_t)cc * NN + ii] = stage[cc * 33 + ii];
    }
}

// ---------------- K6: out BN stats ----------------
__global__ void k_out_stats(const float* __restrict__ gout, const float* __restrict__ bout) {
    __shared__ float sh[512];
    int ch = blockIdx.x;                  // 0..1023 : ch = g*128 + c*2 + t
    int g = ch >> 7, rem = ch & 127, c = rem >> 1, t = rem & 1;
    int tid = threadIdx.x;                // i index
    const float* src = (t ? d_sve : d_sv) + (((size_t)g) * VC + c) * NN + tid;
    float s = 0.f, ss = 0.f;
    for (int b = 0; b < BB; b++) {
        float v = src[(size_t)b * GG * VC * NN];
        s += v; ss += v * v;
    }
    block_reduce2(s, ss, sh);
    if (tid == 0) {
        float m = s / 16384.0f;
        float var = ss / 16384.0f - m * m;
        float a = gout[ch] * rsqrtf(var + EPSV);
        d_outA[ch] = a;
        d_outC[ch] = bout[ch] - m * a;
    }
}

// ---------------- K7: final combine ----------------
__global__ void k_final(float* __restrict__ out) {
    size_t idx = (size_t)blockIdx.x * 256 + threadIdx.x;   // 64*512*256
    int n = idx & 255;
    int pch = (int)((idx >> 8) & 511);
    int b = (int)(idx >> 17);
    int g = pch >> 6, c = pch & 63;
    size_t si = (((size_t)b * GG + g) * VC + c) * NN + n;
    float sv = d_sv[si], sve = d_sve[si];
    int ch0 = pch * 2, ch1 = ch0 + 1;
    out[idx] = d_outA[ch0] * sv + d_outC[ch0] + d_outA[ch1] * sve + d_outC[ch1];
}

// ---------------- launch ----------------
extern "C" void kernel_launch(void* const* d_in, const int* in_sizes, int n_in,
                              void* d_out, int out_size) {
    const float* x    = (const float*)d_in[0];
    const float* wqkv = (const float*)d_in[1];
    const float* rel  = (const float*)d_in[2];
    const float* gq   = (const float*)d_in[3];
    const float* bq   = (const float*)d_in[4];
    const float* gs   = (const float*)d_in[5];
    const float* bs   = (const float*)d_in[6];
    const float* go   = (const float*)d_in[7];
    const float* bo   = (const float*)d_in[8];
    float* out = (float*)d_out;

    size_t smemK3 = (size_t)(32 * 64 + 2 * 32 * 320) * sizeof(float);          // 90112 B
    size_t smemK5 = (size_t)(32 * 257 + 64 * 257 + 64 * 287 + 64 * 33) * sizeof(float); // ~180.6 KB
    cudaFuncSetAttribute(k_sim_raw, cudaFuncAttributeMaxDynamicSharedMemorySize, (int)smemK3);
    cudaFuncSetAttribute(k_attn,    cudaFuncAttributeMaxDynamicSharedMemorySize, (int)smemK5);

    k_zero_stats<<<1, 64>>>();
    {
        dim3 grid(NN / GM, OO / GN, BB);
        k_qkv_gemm<<<grid, 256>>>(x, wqkv);
    }
    k_qkv_stats<<<OO, 256>>>(gq, bq);
    {
        dim3 grid(4, GG, BB);
        k_sim_raw<<<grid, 256, smemK3>>>(rel);
    }
    {
        dim3 grid(8, GG, BB);
        k_attn<<<grid, 256, smemK5>>>(rel, gs, bs);
    }
    k_out_stats<<<OO, 256>>>(go, bo);
    {
        size_t total = (size_t)BB * 512 * NN;
        k_final<<<(unsigned)(total / 256), 256>>>(out);
    }
}